// round 2
// baseline (speedup 1.0000x reference)
#include <cuda_runtime.h>
#include <math.h>

// Shapes are fixed by the problem: B=4, S=8192, D=1024, K=1024, TAU=1.
// M = B*S = 32768 tokens.
//
// Pipeline:
//   k_gemm1    : logits[M,K] = -sqrt(max(|x|^2 + |c|^2 - 2 x.c, 0))
//                (x2 and c2 accumulated inside the GEMM k-loop for free)
//   k_rowstats : per-row max and sum of exp(logits + gumbel) -> __device__ scratch
//   k_gemm2    : quantized[M,D] = softmax_weights[M,K] @ codebook[K,D]
//                (weights recomputed on the fly while loading the A tile)
//
// Output layout (reference returns (quantized, logits)):
//   d_out[0 .. M*D)          = quantized
//   d_out[M*D .. M*D + M*K)  = logits

#define TM 128
#define TN 128
#define TKT 16

// scratch (allocation-free rule: __device__ globals)
__device__ float g_rowmax[32768];
__device__ float g_rowsum[32768];

// ---------------------------------------------------------------------------
// GEMM1: logits
// ---------------------------------------------------------------------------
__global__ __launch_bounds__(256, 2)
void k_gemm1(const float* __restrict__ A,   // [M, D] embeddings (row-major)
             const float* __restrict__ Cb,  // [K, D] codebook   (row-major)
             float* __restrict__ logits,    // [M, K]
             int M, int D, int K)
{
    __shared__ float As[TKT][TM];   // As[kd][m]
    __shared__ float Bs[TKT][TN];   // Bs[kd][n] = Cb[n][kd]   (transposed load)

    const int bm  = blockIdx.y * TM;
    const int bn  = blockIdx.x * TN;
    const int tid = threadIdx.x;
    const int tx  = tid & 15;   // column group (8 cols)
    const int ty  = tid >> 4;   // row group    (8 rows)

    float acc[8][8];
    float x2[8];
    float c2[8];
#pragma unroll
    for (int i = 0; i < 8; i++) {
        x2[i] = 0.f; c2[i] = 0.f;
#pragma unroll
        for (int j = 0; j < 8; j++) acc[i][j] = 0.f;
    }

    for (int k0 = 0; k0 < D; k0 += TKT) {
        // Load A tile (128 rows x 16 kd) transposed into As.
        // Load B tile: codebook rows bn..bn+127 (output columns), 16 kd.
#pragma unroll
        for (int r = 0; r < 2; r++) {
            int idx = tid + r * 256;          // 0..511
            int row = idx >> 2;               // 0..127
            int kq  = (idx & 3) << 2;         // 0,4,8,12
            float4 va = *reinterpret_cast<const float4*>(A  + (size_t)(bm + row) * D + k0 + kq);
            As[kq + 0][row] = va.x;
            As[kq + 1][row] = va.y;
            As[kq + 2][row] = va.z;
            As[kq + 3][row] = va.w;
            float4 vb = *reinterpret_cast<const float4*>(Cb + (size_t)(bn + row) * D + k0 + kq);
            Bs[kq + 0][row] = vb.x;
            Bs[kq + 1][row] = vb.y;
            Bs[kq + 2][row] = vb.z;
            Bs[kq + 3][row] = vb.w;
        }
        __syncthreads();

#pragma unroll
        for (int kk = 0; kk < TKT; kk++) {
            float a[8], b[8];
            *reinterpret_cast<float4*>(&a[0]) = *reinterpret_cast<const float4*>(&As[kk][ty * 8]);
            *reinterpret_cast<float4*>(&a[4]) = *reinterpret_cast<const float4*>(&As[kk][ty * 8 + 4]);
            *reinterpret_cast<float4*>(&b[0]) = *reinterpret_cast<const float4*>(&Bs[kk][tx * 8]);
            *reinterpret_cast<float4*>(&b[4]) = *reinterpret_cast<const float4*>(&Bs[kk][tx * 8 + 4]);
#pragma unroll
            for (int i = 0; i < 8; i++) x2[i] = fmaf(a[i], a[i], x2[i]);
#pragma unroll
            for (int j = 0; j < 8; j++) c2[j] = fmaf(b[j], b[j], c2[j]);
#pragma unroll
            for (int i = 0; i < 8; i++)
#pragma unroll
                for (int j = 0; j < 8; j++)
                    acc[i][j] = fmaf(a[i], b[j], acc[i][j]);
        }
        __syncthreads();
    }

    // Epilogue: d2 = x2 + c2 - 2*xc, logit = -sqrt(max(d2, 0))
#pragma unroll
    for (int i = 0; i < 8; i++) {
        int m = bm + ty * 8 + i;
        float out[8];
#pragma unroll
        for (int j = 0; j < 8; j++) {
            float d2 = x2[i] + c2[j] - 2.0f * acc[i][j];
            d2 = fmaxf(d2, 0.0f);
            out[j] = -sqrtf(d2);
        }
        float* p = logits + (size_t)m * K + bn + tx * 8;
        *reinterpret_cast<float4*>(p)     = *reinterpret_cast<float4*>(&out[0]);
        *reinterpret_cast<float4*>(p + 4) = *reinterpret_cast<float4*>(&out[4]);
    }
}

// ---------------------------------------------------------------------------
// Row softmax stats: z = logits + gumbel, gumbel = -log(-log(u)); TAU = 1
// ---------------------------------------------------------------------------
__global__ __launch_bounds__(256)
void k_rowstats(const float* __restrict__ logits,
                const float* __restrict__ U,
                int K)
{
    __shared__ float red[256];
    const int m = blockIdx.x;
    const int t = threadIdx.x;

    float4 l = *reinterpret_cast<const float4*>(logits + (size_t)m * K + t * 4);
    float4 u = *reinterpret_cast<const float4*>(U      + (size_t)m * K + t * 4);

    float z0 = l.x - logf(-logf(u.x));
    float z1 = l.y - logf(-logf(u.y));
    float z2 = l.z - logf(-logf(u.z));
    float z3 = l.w - logf(-logf(u.w));

    float lm = fmaxf(fmaxf(z0, z1), fmaxf(z2, z3));
    red[t] = lm;
    __syncthreads();
#pragma unroll
    for (int s = 128; s > 0; s >>= 1) {
        if (t < s) red[t] = fmaxf(red[t], red[t + s]);
        __syncthreads();
    }
    float rmax = red[0];
    __syncthreads();

    float se = expf(z0 - rmax) + expf(z1 - rmax) + expf(z2 - rmax) + expf(z3 - rmax);
    red[t] = se;
    __syncthreads();
#pragma unroll
    for (int s = 128; s > 0; s >>= 1) {
        if (t < s) red[t] += red[t + s];
        __syncthreads();
    }
    if (t == 0) {
        g_rowmax[m] = rmax;
        g_rowsum[m] = red[0];
    }
}

// ---------------------------------------------------------------------------
// GEMM2: quantized = weights @ codebook; weights computed during A-tile load
// ---------------------------------------------------------------------------
__global__ __launch_bounds__(256, 2)
void k_gemm2(const float* __restrict__ logits,  // [M, K]
             const float* __restrict__ U,       // [M, K]
             const float* __restrict__ Cb,      // [K, D]
             float* __restrict__ Q,             // [M, D]
             int M, int D, int K)
{
    __shared__ float As[TKT][TM];   // As[kd][m] = weight
    __shared__ float Bs[TKT][TN];   // Bs[kd][n] = Cb[k0+kd][bn+n]

    const int bm  = blockIdx.y * TM;
    const int bn  = blockIdx.x * TN;
    const int tid = threadIdx.x;
    const int tx  = tid & 15;
    const int ty  = tid >> 4;

    float acc[8][8];
#pragma unroll
    for (int i = 0; i < 8; i++)
#pragma unroll
        for (int j = 0; j < 8; j++) acc[i][j] = 0.f;

    for (int k0 = 0; k0 < K; k0 += TKT) {
        // A tile: softmax weights recomputed from logits + noise + row stats
#pragma unroll
        for (int r = 0; r < 2; r++) {
            int idx = tid + r * 256;
            int row = idx >> 2;
            int kq  = (idx & 3) << 2;
            int m   = bm + row;
            float4 l = *reinterpret_cast<const float4*>(logits + (size_t)m * K + k0 + kq);
            float4 u = *reinterpret_cast<const float4*>(U      + (size_t)m * K + k0 + kq);
            float rmax = g_rowmax[m];
            float rinv = 1.0f / g_rowsum[m];
            As[kq + 0][row] = expf(l.x - logf(-logf(u.x)) - rmax) * rinv;
            As[kq + 1][row] = expf(l.y - logf(-logf(u.y)) - rmax) * rinv;
            As[kq + 2][row] = expf(l.z - logf(-logf(u.z)) - rmax) * rinv;
            As[kq + 3][row] = expf(l.w - logf(-logf(u.w)) - rmax) * rinv;
        }
        // B tile: contiguous rows of the codebook
#pragma unroll
        for (int r = 0; r < 2; r++) {
            int idx = tid + r * 256;
            int kd  = idx >> 5;           // 0..15
            int nq  = (idx & 31) << 2;    // 0..124
            float4 v = *reinterpret_cast<const float4*>(Cb + (size_t)(k0 + kd) * D + bn + nq);
            *reinterpret_cast<float4*>(&Bs[kd][nq]) = v;
        }
        __syncthreads();

#pragma unroll
        for (int kk = 0; kk < TKT; kk++) {
            float a[8], b[8];
            *reinterpret_cast<float4*>(&a[0]) = *reinterpret_cast<const float4*>(&As[kk][ty * 8]);
            *reinterpret_cast<float4*>(&a[4]) = *reinterpret_cast<const float4*>(&As[kk][ty * 8 + 4]);
            *reinterpret_cast<float4*>(&b[0]) = *reinterpret_cast<const float4*>(&Bs[kk][tx * 8]);
            *reinterpret_cast<float4*>(&b[4]) = *reinterpret_cast<const float4*>(&Bs[kk][tx * 8 + 4]);
#pragma unroll
            for (int i = 0; i < 8; i++)
#pragma unroll
                for (int j = 0; j < 8; j++)
                    acc[i][j] = fmaf(a[i], b[j], acc[i][j]);
        }
        __syncthreads();
    }

#pragma unroll
    for (int i = 0; i < 8; i++) {
        int m = bm + ty * 8 + i;
        float* p = Q + (size_t)m * D + bn + tx * 8;
        *reinterpret_cast<float4*>(p)     = *reinterpret_cast<float4*>(&acc[i][0]);
        *reinterpret_cast<float4*>(p + 4) = *reinterpret_cast<float4*>(&acc[i][4]);
    }
}

// ---------------------------------------------------------------------------
extern "C" void kernel_launch(void* const* d_in, const int* in_sizes, int n_in,
                              void* d_out, int out_size)
{
    const float* emb = (const float*)d_in[0];  // [M, D]
    const float* cb  = (const float*)d_in[1];  // [K, D]
    const float* un  = (const float*)d_in[2];  // [M, K]

    const int D = 1024;
    const int K = 1024;
    const int M = in_sizes[0] / D;             // 32768

    float* quant  = (float*)d_out;                       // [M, D]
    float* logits = (float*)d_out + (size_t)M * D;       // [M, K]

    dim3 blk(256);
    dim3 g1(K / TN, M / TM);   // (8, 256)
    k_gemm1<<<g1, blk>>>(emb, cb, logits, M, D, K);

    k_rowstats<<<M, 256>>>(logits, un, K);

    dim3 g2(D / TN, M / TM);   // (8, 256)
    k_gemm2<<<g2, blk>>>(logits, un, cb, quant, M, D, K);
}

// round 8
// speedup vs baseline: 2.8550x; 2.8550x over previous
#include <cuda_runtime.h>
#include <cuda_bf16.h>
#include <mma.h>
#include <math.h>
#include <stdint.h>

using namespace nvcuda;

// Problem shapes (fixed): B=4, S=8192, D=1024, K=1024, TAU=1. M = B*S = 32768.
// Toolchain-proven profile: plain sm_100 PTX; no tcgen05; no hand mma/ldmatrix
// asm (wmma API only); cp.async asm (proven in R4 log); static smem <= 48KB;
// no runtime attribute calls; default stream.
#define M_TOK 32768
#define DDIM  1024
#define KCB   1024

#define BK    32
#define LDT   40            // padded smem row pitch (elements); r*20 mod 32 distinct
#define TILE_B (128 * LDT * 2)   // 10240 bytes per [128 x BK] bf16 tile

// ---------------------------------------------------------------------------
// Scratch (__device__ globals; allocation-free rule)
// ---------------------------------------------------------------------------
__device__ __align__(1024) __nv_bfloat16 g_embh[(size_t)M_TOK * DDIM]; // emb    [M,D]
__device__ __align__(1024) __nv_bfloat16 g_cbh [(size_t)KCB * DDIM];   // cb hi  [K,D]
__device__ __align__(1024) __nv_bfloat16 g_cbth[(size_t)DDIM * KCB];   // cb^T hi[D,K]
__device__ __align__(1024) __nv_bfloat16 g_cbtl[(size_t)DDIM * KCB];   // cb^T lo[D,K]
__device__ __align__(1024) __nv_bfloat16 g_wh  [(size_t)M_TOK * KCB];  // W hi   [M,K]
__device__ __align__(1024) __nv_bfloat16 g_wl  [(size_t)M_TOK * KCB];  // W lo   [M,K]
__device__ float g_x2[M_TOK];
__device__ float g_c2[KCB];

// ---------------------------------------------------------------------------
// cp.async helpers (proven on this toolchain by the R4 ptxas log)
// ---------------------------------------------------------------------------
__device__ __forceinline__ uint32_t s2u(const void* p) {
    return (uint32_t)__cvta_generic_to_shared(p);
}
#define CP_ASYNC16(dst, src) \
    asm volatile("cp.async.cg.shared.global [%0], [%1], 16;" :: "r"(dst), "l"(src) : "memory")
#define CP_COMMIT() asm volatile("cp.async.commit_group;" ::: "memory")
#define CP_WAIT0()  asm volatile("cp.async.wait_group 0;" ::: "memory")
#define CP_WAIT1()  asm volatile("cp.async.wait_group 1;" ::: "memory")

// Load one [128 x BK] bf16 tile into padded smem (row pitch LDT elements).
// All source matrices have row pitch 1024 bf16. 512 chunks, 256 threads x 2.
__device__ __forceinline__ void load_tile(uint32_t dst, const __nv_bfloat16* src,
                                          int row0, int k0, int tid) {
#pragma unroll
    for (int q = 0; q < 2; q++) {
        int c = tid + q * 256;            // 0..511 = 128 rows x 4 chunks of 16B
        int row = c >> 2, cc = c & 3;
        CP_ASYNC16(dst + (uint32_t)row * (LDT * 2) + (uint32_t)cc * 16,
                   src + (size_t)(row0 + row) * 1024 + k0 + cc * 8);
    }
}

typedef wmma::fragment<wmma::matrix_a, 16, 16, 16, __nv_bfloat16, wmma::row_major> FragA;
typedef wmma::fragment<wmma::matrix_b, 16, 16, 16, __nv_bfloat16, wmma::col_major> FragB;
typedef wmma::fragment<wmma::accumulator, 16, 16, 16, float> FragC;

// ---------------------------------------------------------------------------
// Prep: embeddings -> bf16 + exact fp32 row norms
// ---------------------------------------------------------------------------
__global__ __launch_bounds__(256) void k_prep_emb(const float* __restrict__ E) {
    __shared__ float sred[8];
    const int m = blockIdx.x;
    const int t = threadIdx.x;
    float4 v = *reinterpret_cast<const float4*>(E + (size_t)m * DDIM + t * 4);
    __nv_bfloat16* dst = g_embh + (size_t)m * DDIM + t * 4;
    *reinterpret_cast<__nv_bfloat162*>(dst)     = __float22bfloat162_rn(make_float2(v.x, v.y));
    *reinterpret_cast<__nv_bfloat162*>(dst + 2) = __float22bfloat162_rn(make_float2(v.z, v.w));
    float s = v.x * v.x + v.y * v.y + v.z * v.z + v.w * v.w;
#pragma unroll
    for (int o = 16; o > 0; o >>= 1) s += __shfl_xor_sync(0xFFFFFFFFu, s, o);
    if ((t & 31) == 0) sred[t >> 5] = s;
    __syncthreads();
    if (t == 0) {
        float tot = 0.f;
#pragma unroll
        for (int i = 0; i < 8; i++) tot += sred[i];
        g_x2[m] = tot;
    }
}

// ---------------------------------------------------------------------------
// Prep: codebook -> bf16 hi [K,D], transposed hi/lo [D,K], exact fp32 norms
// ---------------------------------------------------------------------------
__global__ __launch_bounds__(256) void k_prep_cb(const float* __restrict__ C) {
    __shared__ float sred[8];
    const int k = blockIdx.x;
    const int t = threadIdx.x;
    float4 v = *reinterpret_cast<const float4*>(C + (size_t)k * DDIM + t * 4);
    float vv[4] = {v.x, v.y, v.z, v.w};
    __nv_bfloat16 hi[4], lo[4];
#pragma unroll
    for (int j = 0; j < 4; j++) {
        hi[j] = __float2bfloat16_rn(vv[j]);
        lo[j] = __float2bfloat16_rn(vv[j] - __bfloat162float(hi[j]));
    }
    __nv_bfloat16* dst = g_cbh + (size_t)k * DDIM + t * 4;
    *reinterpret_cast<__nv_bfloat162*>(dst)     = __nv_bfloat162(hi[0], hi[1]);
    *reinterpret_cast<__nv_bfloat162*>(dst + 2) = __nv_bfloat162(hi[2], hi[3]);
#pragma unroll
    for (int j = 0; j < 4; j++) {
        int d = t * 4 + j;
        g_cbth[(size_t)d * KCB + k] = hi[j];
        g_cbtl[(size_t)d * KCB + k] = lo[j];
    }
    float s = v.x * v.x + v.y * v.y + v.z * v.z + v.w * v.w;
#pragma unroll
    for (int o = 16; o > 0; o >>= 1) s += __shfl_xor_sync(0xFFFFFFFFu, s, o);
    if ((t & 31) == 0) sred[t >> 5] = s;
    __syncthreads();
    if (t == 0) {
        float tot = 0.f;
#pragma unroll
        for (int i = 0; i < 8; i++) tot += sred[i];
        g_c2[k] = tot;
    }
}

// ---------------------------------------------------------------------------
// GEMM1: logits[M,K] = -sqrt(max(x2 + c2 - 2 * (emb @ cb^T), 0))
// 128x128 CTA, BK=32, double-buffered cp.async, wmma bf16, 40KB static smem.
// ---------------------------------------------------------------------------
__global__ __launch_bounds__(256) void k_gemm1(float* __restrict__ out)
{
    __shared__ __align__(1024) char sm[2 * 2 * TILE_B];   // [A|B] x 2 buffers
    const uint32_t sbase = s2u(sm);
    const int tid  = threadIdx.x;
    const int lane = tid & 31;
    const int warp = tid >> 5;
    const int wm = (warp >> 2) * 64;
    const int wn = (warp & 3) * 32;
    const int bm = blockIdx.y * 128, bn = blockIdx.x * 128;

    FragC acc[4][2];
#pragma unroll
    for (int i = 0; i < 4; i++)
#pragma unroll
        for (int j = 0; j < 2; j++) wmma::fill_fragment(acc[i][j], 0.0f);

    load_tile(sbase,          g_embh, bm, 0, tid);
    load_tile(sbase + TILE_B, g_cbh,  bn, 0, tid);
    CP_COMMIT();

    for (int s = 0; s < 32; s++) {
        const uint32_t buf = sbase + (uint32_t)(s & 1) * (2 * TILE_B);
        if (s + 1 < 32) {
            const uint32_t nb = sbase + (uint32_t)((s + 1) & 1) * (2 * TILE_B);
            load_tile(nb,          g_embh, bm, (s + 1) * BK, tid);
            load_tile(nb + TILE_B, g_cbh,  bn, (s + 1) * BK, tid);
            CP_COMMIT();
            CP_WAIT1();
        } else {
            CP_WAIT0();
        }
        __syncthreads();

        const __nv_bfloat16* As = (const __nv_bfloat16*)(sm + (buf - sbase));
        const __nv_bfloat16* Bs = As + TILE_B / 2;
#pragma unroll
        for (int ks = 0; ks < 2; ks++) {
            FragA a[4];
            FragB b[2];
#pragma unroll
            for (int i = 0; i < 4; i++)
                wmma::load_matrix_sync(a[i], As + (wm + i * 16) * LDT + ks * 16, LDT);
#pragma unroll
            for (int j = 0; j < 2; j++)
                wmma::load_matrix_sync(b[j], Bs + (wn + j * 16) * LDT + ks * 16, LDT);
#pragma unroll
            for (int i = 0; i < 4; i++)
#pragma unroll
                for (int j = 0; j < 2; j++)
                    wmma::mma_sync(acc[i][j], a[i], b[j], acc[i][j]);
        }
        __syncthreads();
    }

    // epilogue via per-warp smem staging (reuses tile buffer)
    __syncthreads();
    float* stg = reinterpret_cast<float*>(sm) + warp * 256;   // 16x16, ld=16
#pragma unroll
    for (int i = 0; i < 4; i++)
#pragma unroll
        for (int j = 0; j < 2; j++) {
            wmma::store_matrix_sync(stg, acc[i][j], 16, wmma::mem_row_major);
            __syncwarp();
            const int r  = lane >> 1;
            const int c0 = (lane & 1) * 8;
            const int m0 = bm + wm + i * 16 + r;
            const int n0 = bn + wn + j * 16 + c0;
            const float x2m = g_x2[m0];
            float o[8];
#pragma unroll
            for (int t2 = 0; t2 < 8; t2++) {
                float d2 = x2m + g_c2[n0 + t2] - 2.0f * stg[r * 16 + c0 + t2];
                o[t2] = -sqrtf(fmaxf(d2, 0.0f));
            }
            float* p = out + (size_t)m0 * KCB + n0;
            *reinterpret_cast<float4*>(p)     = make_float4(o[0], o[1], o[2], o[3]);
            *reinterpret_cast<float4*>(p + 4) = make_float4(o[4], o[5], o[6], o[7]);
            __syncwarp();
        }
}

// ---------------------------------------------------------------------------
// Softmax row pass: w = softmax(logits + gumbel), split into bf16 hi/lo
// ---------------------------------------------------------------------------
__global__ __launch_bounds__(256) void k_softmax(const float* __restrict__ L,
                                                 const float* __restrict__ U)
{
    __shared__ float sred[8];
    __shared__ float sbro[2];
    const int m = blockIdx.x;
    const int t = threadIdx.x;
    float4 l = *reinterpret_cast<const float4*>(L + (size_t)m * KCB + t * 4);
    float4 u = *reinterpret_cast<const float4*>(U + (size_t)m * KCB + t * 4);

    float z[4];
    z[0] = l.x - logf(-logf(u.x));
    z[1] = l.y - logf(-logf(u.y));
    z[2] = l.z - logf(-logf(u.z));
    z[3] = l.w - logf(-logf(u.w));

    float mx = fmaxf(fmaxf(z[0], z[1]), fmaxf(z[2], z[3]));
#pragma unroll
    for (int o = 16; o > 0; o >>= 1) mx = fmaxf(mx, __shfl_xor_sync(0xFFFFFFFFu, mx, o));
    if ((t & 31) == 0) sred[t >> 5] = mx;
    __syncthreads();
    if (t == 0) {
        float r = sred[0];
#pragma unroll
        for (int i = 1; i < 8; i++) r = fmaxf(r, sred[i]);
        sbro[0] = r;
    }
    __syncthreads();
    const float rmax = sbro[0];

    float e[4];
#pragma unroll
    for (int j = 0; j < 4; j++) e[j] = expf(z[j] - rmax);
    float s = e[0] + e[1] + e[2] + e[3];
#pragma unroll
    for (int o = 16; o > 0; o >>= 1) s += __shfl_xor_sync(0xFFFFFFFFu, s, o);
    if ((t & 31) == 0) sred[t >> 5] = s;
    __syncthreads();
    if (t == 0) {
        float r = 0.f;
#pragma unroll
        for (int i = 0; i < 8; i++) r += sred[i];
        sbro[1] = 1.0f / r;
    }
    __syncthreads();
    const float rinv = sbro[1];

    __nv_bfloat16 hi[4], lo[4];
#pragma unroll
    for (int j = 0; j < 4; j++) {
        float w = e[j] * rinv;
        hi[j] = __float2bfloat16_rn(w);
        lo[j] = __float2bfloat16_rn(w - __bfloat162float(hi[j]));
    }
    __nv_bfloat16* dh = g_wh + (size_t)m * KCB + t * 4;
    __nv_bfloat16* dl = g_wl + (size_t)m * KCB + t * 4;
    *reinterpret_cast<__nv_bfloat162*>(dh)     = __nv_bfloat162(hi[0], hi[1]);
    *reinterpret_cast<__nv_bfloat162*>(dh + 2) = __nv_bfloat162(hi[2], hi[3]);
    *reinterpret_cast<__nv_bfloat162*>(dl)     = __nv_bfloat162(lo[0], lo[1]);
    *reinterpret_cast<__nv_bfloat162*>(dl + 2) = __nv_bfloat162(lo[2], lo[3]);
}

// ---------------------------------------------------------------------------
// GEMM2a: Q[M,D] = Wh @ Ch^T   (write)
// GEMM2b: Q[M,D] += Wh @ Cl^T + Wl @ Ch^T   (virtual K=2048, one RMW pass)
// ---------------------------------------------------------------------------
__device__ __forceinline__ void g2_sources(int s, int nstages,
                                           const __nv_bfloat16** A,
                                           const __nv_bfloat16** B, int* k0) {
    if (nstages == 32) {                 // gemm2a: Wh . Ch
        *A = g_wh; *B = g_cbth; *k0 = s * BK;
    } else {                             // gemm2b: s<32: Wh . Cl ; s>=32: Wl . Ch
        if (s < 32) { *A = g_wh; *B = g_cbtl; }
        else        { *A = g_wl; *B = g_cbth; }
        *k0 = (s & 31) * BK;
    }
}

template <int NSTAGES, bool RMW>
__device__ __forceinline__ void gemm2_body(float* __restrict__ out) {
    __shared__ __align__(1024) char sm[2 * 2 * TILE_B];
    const uint32_t sbase = s2u(sm);
    const int tid  = threadIdx.x;
    const int lane = tid & 31;
    const int warp = tid >> 5;
    const int wm = (warp >> 2) * 64;
    const int wn = (warp & 3) * 32;
    const int bm = blockIdx.y * 128, bn = blockIdx.x * 128;

    FragC acc[4][2];
#pragma unroll
    for (int i = 0; i < 4; i++)
#pragma unroll
        for (int j = 0; j < 2; j++) wmma::fill_fragment(acc[i][j], 0.0f);

    {
        const __nv_bfloat16 *A, *B; int k0;
        g2_sources(0, NSTAGES, &A, &B, &k0);
        load_tile(sbase,          A, bm, k0, tid);
        load_tile(sbase + TILE_B, B, bn, k0, tid);
        CP_COMMIT();
    }

    for (int s = 0; s < NSTAGES; s++) {
        const uint32_t buf = sbase + (uint32_t)(s & 1) * (2 * TILE_B);
        if (s + 1 < NSTAGES) {
            const uint32_t nb = sbase + (uint32_t)((s + 1) & 1) * (2 * TILE_B);
            const __nv_bfloat16 *A, *B; int k0;
            g2_sources(s + 1, NSTAGES, &A, &B, &k0);
            load_tile(nb,          A, bm, k0, tid);
            load_tile(nb + TILE_B, B, bn, k0, tid);
            CP_COMMIT();
            CP_WAIT1();
        } else {
            CP_WAIT0();
        }
        __syncthreads();

        const __nv_bfloat16* As = (const __nv_bfloat16*)(sm + (buf - sbase));
        const __nv_bfloat16* Bs = As + TILE_B / 2;
#pragma unroll
        for (int ks = 0; ks < 2; ks++) {
            FragA a[4];
            FragB b[2];
#pragma unroll
            for (int i = 0; i < 4; i++)
                wmma::load_matrix_sync(a[i], As + (wm + i * 16) * LDT + ks * 16, LDT);
#pragma unroll
            for (int j = 0; j < 2; j++)
                wmma::load_matrix_sync(b[j], Bs + (wn + j * 16) * LDT + ks * 16, LDT);
#pragma unroll
            for (int i = 0; i < 4; i++)
#pragma unroll
                for (int j = 0; j < 2; j++)
                    wmma::mma_sync(acc[i][j], a[i], b[j], acc[i][j]);
        }
        __syncthreads();
    }

    __syncthreads();
    float* stg = reinterpret_cast<float*>(sm) + warp * 256;
#pragma unroll
    for (int i = 0; i < 4; i++)
#pragma unroll
        for (int j = 0; j < 2; j++) {
            wmma::store_matrix_sync(stg, acc[i][j], 16, wmma::mem_row_major);
            __syncwarp();
            const int r  = lane >> 1;
            const int c0 = (lane & 1) * 8;
            const int m0 = bm + wm + i * 16 + r;
            const int n0 = bn + wn + j * 16 + c0;
            float* p = out + (size_t)m0 * DDIM + n0;
            if (RMW) {
                float4 v0 = *reinterpret_cast<float4*>(p);
                float4 v1 = *reinterpret_cast<float4*>(p + 4);
                v0.x += stg[r * 16 + c0 + 0]; v0.y += stg[r * 16 + c0 + 1];
                v0.z += stg[r * 16 + c0 + 2]; v0.w += stg[r * 16 + c0 + 3];
                v1.x += stg[r * 16 + c0 + 4]; v1.y += stg[r * 16 + c0 + 5];
                v1.z += stg[r * 16 + c0 + 6]; v1.w += stg[r * 16 + c0 + 7];
                *reinterpret_cast<float4*>(p)     = v0;
                *reinterpret_cast<float4*>(p + 4) = v1;
            } else {
                *reinterpret_cast<float4*>(p) =
                    make_float4(stg[r * 16 + c0 + 0], stg[r * 16 + c0 + 1],
                                stg[r * 16 + c0 + 2], stg[r * 16 + c0 + 3]);
                *reinterpret_cast<float4*>(p + 4) =
                    make_float4(stg[r * 16 + c0 + 4], stg[r * 16 + c0 + 5],
                                stg[r * 16 + c0 + 6], stg[r * 16 + c0 + 7]);
            }
            __syncwarp();
        }
}

__global__ __launch_bounds__(256) void k_gemm2a(float* __restrict__ out) {
    gemm2_body<32, false>(out);
}
__global__ __launch_bounds__(256) void k_gemm2b(float* __restrict__ out) {
    gemm2_body<64, true>(out);
}

// ---------------------------------------------------------------------------
// Host
// ---------------------------------------------------------------------------
extern "C" void kernel_launch(void* const* d_in, const int* in_sizes, int n_in,
                              void* d_out, int out_size)
{
    const float* emb = (const float*)d_in[0];   // [M, D]
    const float* cb  = (const float*)d_in[1];   // [K, D]
    const float* un  = (const float*)d_in[2];   // [M, K]

    float* quant  = (float*)d_out;                         // [M, D]
    float* logits = (float*)d_out + (size_t)M_TOK * DDIM;  // [M, K]

    k_prep_emb<<<M_TOK, 256>>>(emb);
    k_prep_cb<<<KCB, 256>>>(cb);
    k_gemm1<<<dim3(KCB / 128, M_TOK / 128), 256>>>(logits);
    k_softmax<<<M_TOK, 256>>>(logits, un);
    k_gemm2a<<<dim3(DDIM / 128, M_TOK / 128), 256>>>(quant);
    k_gemm2b<<<dim3(DDIM / 128, M_TOK / 128), 256>>>(quant);
}

// round 9
// speedup vs baseline: 4.3713x; 1.5311x over previous
#include <cuda_runtime.h>
#include <cuda_fp16.h>
#include <mma.h>
#include <math.h>
#include <stdint.h>

using namespace nvcuda;

// Problem shapes (fixed): B=4, S=8192, D=1024, K=1024, TAU=1. M = B*S = 32768.
// Proven toolchain envelope: plain sm_100 PTX, wmma API (no hand mma/ldmatrix
// asm, no tcgen05), cp.async asm, static smem <= 48KB, no attribute calls,
// default stream.
#define M_TOK 32768
#define DDIM  1024
#define KCB   1024

#define BK    32
#define LDT   40                   // pad: r*20 mod 32 distinct -> conflict-free
#define TILE_B (128 * LDT * 2)     // 10240 B per [128 x 32] fp16 tile

#define BK2   16
#define LDT2  24                   // pad: r*12 mod 32 distinct -> conflict-free
#define TILE2 (128 * LDT2 * 2)     // 6144 B per [128 x 16] fp16 tile

// ---------------------------------------------------------------------------
// Scratch (__device__ globals; allocation-free rule)
// ---------------------------------------------------------------------------
__device__ __align__(1024) __half g_embh[(size_t)M_TOK * DDIM]; // emb     [M,D]
__device__ __align__(1024) __half g_cbh [(size_t)KCB * DDIM];   // cb      [K,D]
__device__ __align__(1024) __half g_cbth[(size_t)DDIM * KCB];   // cb^T    [D,K]
__device__ __align__(1024) __half g_wh  [(size_t)M_TOK * KCB];  // W hi    [M,K]
__device__ __align__(1024) __half g_wl  [(size_t)M_TOK * KCB];  // W lo    [M,K]
__device__ float g_x2[M_TOK];
__device__ float g_c2[KCB];

// ---------------------------------------------------------------------------
// cp.async helpers (proven on this toolchain)
// ---------------------------------------------------------------------------
__device__ __forceinline__ uint32_t s2u(const void* p) {
    return (uint32_t)__cvta_generic_to_shared(p);
}
#define CP_ASYNC16(dst, src) \
    asm volatile("cp.async.cg.shared.global [%0], [%1], 16;" :: "r"(dst), "l"(src) : "memory")
#define CP_COMMIT() asm volatile("cp.async.commit_group;" ::: "memory")
#define CP_WAIT0()  asm volatile("cp.async.wait_group 0;" ::: "memory")
#define CP_WAIT1()  asm volatile("cp.async.wait_group 1;" ::: "memory")

// [128 x 32] fp16 tile, row pitch LDT elements; 256 threads x 2 chunks of 16B.
__device__ __forceinline__ void load_tile32(uint32_t dst, const __half* src,
                                            int row0, int k0, int tid) {
#pragma unroll
    for (int q = 0; q < 2; q++) {
        int c = tid + q * 256;            // 0..511 = 128 rows x 4 chunks
        int row = c >> 2, cc = c & 3;
        CP_ASYNC16(dst + (uint32_t)row * (LDT * 2) + (uint32_t)cc * 16,
                   src + (size_t)(row0 + row) * 1024 + k0 + cc * 8);
    }
}
// [128 x 16] fp16 tile, row pitch LDT2 elements; 256 threads x 1 chunk.
__device__ __forceinline__ void load_tile16(uint32_t dst, const __half* src,
                                            int row0, int k0, int tid) {
    int row = tid >> 1, cc = tid & 1;
    CP_ASYNC16(dst + (uint32_t)row * (LDT2 * 2) + (uint32_t)cc * 16,
               src + (size_t)(row0 + row) * 1024 + k0 + cc * 8);
}

typedef wmma::fragment<wmma::matrix_a, 16, 16, 16, __half, wmma::row_major> FragA;
typedef wmma::fragment<wmma::matrix_b, 16, 16, 16, __half, wmma::col_major> FragB;
typedef wmma::fragment<wmma::accumulator, 16, 16, 16, float> FragC;

// ---------------------------------------------------------------------------
// Prep: embeddings -> fp16 + exact fp32 row norms
// ---------------------------------------------------------------------------
__global__ __launch_bounds__(256) void k_prep_emb(const float* __restrict__ E) {
    __shared__ float sred[8];
    const int m = blockIdx.x;
    const int t = threadIdx.x;
    float4 v = *reinterpret_cast<const float4*>(E + (size_t)m * DDIM + t * 4);
    __half* dst = g_embh + (size_t)m * DDIM + t * 4;
    *reinterpret_cast<__half2*>(dst)     = __floats2half2_rn(v.x, v.y);
    *reinterpret_cast<__half2*>(dst + 2) = __floats2half2_rn(v.z, v.w);
    float s = v.x * v.x + v.y * v.y + v.z * v.z + v.w * v.w;
#pragma unroll
    for (int o = 16; o > 0; o >>= 1) s += __shfl_xor_sync(0xFFFFFFFFu, s, o);
    if ((t & 31) == 0) sred[t >> 5] = s;
    __syncthreads();
    if (t == 0) {
        float tot = 0.f;
#pragma unroll
        for (int i = 0; i < 8; i++) tot += sred[i];
        g_x2[m] = tot;
    }
}

// ---------------------------------------------------------------------------
// Prep: codebook -> fp16 [K,D], transposed fp16 [D,K], exact fp32 norms
// ---------------------------------------------------------------------------
__global__ __launch_bounds__(256) void k_prep_cb(const float* __restrict__ C) {
    __shared__ float sred[8];
    const int k = blockIdx.x;
    const int t = threadIdx.x;
    float4 v = *reinterpret_cast<const float4*>(C + (size_t)k * DDIM + t * 4);
    __half h0 = __float2half_rn(v.x), h1 = __float2half_rn(v.y);
    __half h2 = __float2half_rn(v.z), h3 = __float2half_rn(v.w);
    __half* dst = g_cbh + (size_t)k * DDIM + t * 4;
    *reinterpret_cast<__half2*>(dst)     = __half2(h0, h1);
    *reinterpret_cast<__half2*>(dst + 2) = __half2(h2, h3);
    g_cbth[(size_t)(t * 4 + 0) * KCB + k] = h0;
    g_cbth[(size_t)(t * 4 + 1) * KCB + k] = h1;
    g_cbth[(size_t)(t * 4 + 2) * KCB + k] = h2;
    g_cbth[(size_t)(t * 4 + 3) * KCB + k] = h3;
    float s = v.x * v.x + v.y * v.y + v.z * v.z + v.w * v.w;
#pragma unroll
    for (int o = 16; o > 0; o >>= 1) s += __shfl_xor_sync(0xFFFFFFFFu, s, o);
    if ((t & 31) == 0) sred[t >> 5] = s;
    __syncthreads();
    if (t == 0) {
        float tot = 0.f;
#pragma unroll
        for (int i = 0; i < 8; i++) tot += sred[i];
        g_c2[k] = tot;
    }
}

// ---------------------------------------------------------------------------
// GEMM1: logits[M,K] = -sqrt(max(x2 + c2 - 2 * (emb @ cb^T), 0))
// 128x128 CTA, BK=32, double-buffered cp.async, wmma fp16, 40KB static smem.
// ---------------------------------------------------------------------------
__global__ __launch_bounds__(256) void k_gemm1(float* __restrict__ out)
{
    __shared__ __align__(1024) char sm[2 * 2 * TILE_B];   // [A|B] x 2 buffers
    const uint32_t sbase = s2u(sm);
    const int tid  = threadIdx.x;
    const int lane = tid & 31;
    const int warp = tid >> 5;
    const int wm = (warp >> 2) * 64;
    const int wn = (warp & 3) * 32;
    const int bm = blockIdx.y * 128, bn = blockIdx.x * 128;

    FragC acc[4][2];
#pragma unroll
    for (int i = 0; i < 4; i++)
#pragma unroll
        for (int j = 0; j < 2; j++) wmma::fill_fragment(acc[i][j], 0.0f);

    load_tile32(sbase,          g_embh, bm, 0, tid);
    load_tile32(sbase + TILE_B, g_cbh,  bn, 0, tid);
    CP_COMMIT();

    for (int s = 0; s < 32; s++) {
        const uint32_t buf = sbase + (uint32_t)(s & 1) * (2 * TILE_B);
        if (s + 1 < 32) {
            const uint32_t nb = sbase + (uint32_t)((s + 1) & 1) * (2 * TILE_B);
            load_tile32(nb,          g_embh, bm, (s + 1) * BK, tid);
            load_tile32(nb + TILE_B, g_cbh,  bn, (s + 1) * BK, tid);
            CP_COMMIT();
            CP_WAIT1();
        } else {
            CP_WAIT0();
        }
        __syncthreads();

        const __half* As = (const __half*)(sm + (buf - sbase));
        const __half* Bs = (const __half*)(sm + (buf - sbase) + TILE_B);
#pragma unroll
        for (int ks = 0; ks < 2; ks++) {
            FragA a[4];
            FragB b[2];
#pragma unroll
            for (int i = 0; i < 4; i++)
                wmma::load_matrix_sync(a[i], As + (wm + i * 16) * LDT + ks * 16, LDT);
#pragma unroll
            for (int j = 0; j < 2; j++)
                wmma::load_matrix_sync(b[j], Bs + (wn + j * 16) * LDT + ks * 16, LDT);
#pragma unroll
            for (int i = 0; i < 4; i++)
#pragma unroll
                for (int j = 0; j < 2; j++)
                    wmma::mma_sync(acc[i][j], a[i], b[j], acc[i][j]);
        }
        __syncthreads();
    }

    // epilogue via per-warp smem staging
    __syncthreads();
    float* stg = reinterpret_cast<float*>(sm) + warp * 256;   // 16x16, ld=16
#pragma unroll
    for (int i = 0; i < 4; i++)
#pragma unroll
        for (int j = 0; j < 2; j++) {
            wmma::store_matrix_sync(stg, acc[i][j], 16, wmma::mem_row_major);
            __syncwarp();
            const int r  = lane >> 1;
            const int c0 = (lane & 1) * 8;
            const int m0 = bm + wm + i * 16 + r;
            const int n0 = bn + wn + j * 16 + c0;
            const float x2m = g_x2[m0];
            float o[8];
#pragma unroll
            for (int t2 = 0; t2 < 8; t2++) {
                float d2 = x2m + g_c2[n0 + t2] - 2.0f * stg[r * 16 + c0 + t2];
                o[t2] = -sqrtf(fmaxf(d2, 0.0f));
            }
            float* p = out + (size_t)m0 * KCB + n0;
            *reinterpret_cast<float4*>(p)     = make_float4(o[0], o[1], o[2], o[3]);
            *reinterpret_cast<float4*>(p + 4) = make_float4(o[4], o[5], o[6], o[7]);
            __syncwarp();
        }
}

// ---------------------------------------------------------------------------
// Softmax row pass: w = softmax(logits + gumbel), split into fp16 hi/lo.
// Fast-math log/exp (alu was the measured bottleneck at 54.6%).
// ---------------------------------------------------------------------------
__global__ __launch_bounds__(256) void k_softmax(const float* __restrict__ L,
                                                 const float* __restrict__ U)
{
    __shared__ float sred[8];
    __shared__ float sbro[2];
    const int m = blockIdx.x;
    const int t = threadIdx.x;
    float4 l = *reinterpret_cast<const float4*>(L + (size_t)m * KCB + t * 4);
    float4 u = *reinterpret_cast<const float4*>(U + (size_t)m * KCB + t * 4);

    float z[4];
    z[0] = l.x - __logf(-__logf(u.x));
    z[1] = l.y - __logf(-__logf(u.y));
    z[2] = l.z - __logf(-__logf(u.z));
    z[3] = l.w - __logf(-__logf(u.w));

    float mx = fmaxf(fmaxf(z[0], z[1]), fmaxf(z[2], z[3]));
#pragma unroll
    for (int o = 16; o > 0; o >>= 1) mx = fmaxf(mx, __shfl_xor_sync(0xFFFFFFFFu, mx, o));
    if ((t & 31) == 0) sred[t >> 5] = mx;
    __syncthreads();
    if (t == 0) {
        float r = sred[0];
#pragma unroll
        for (int i = 1; i < 8; i++) r = fmaxf(r, sred[i]);
        sbro[0] = r;
    }
    __syncthreads();
    const float rmax = sbro[0];

    float e[4];
#pragma unroll
    for (int j = 0; j < 4; j++) e[j] = __expf(z[j] - rmax);
    float s = e[0] + e[1] + e[2] + e[3];
#pragma unroll
    for (int o = 16; o > 0; o >>= 1) s += __shfl_xor_sync(0xFFFFFFFFu, s, o);
    if ((t & 31) == 0) sred[t >> 5] = s;
    __syncthreads();
    if (t == 0) {
        float r = 0.f;
#pragma unroll
        for (int i = 0; i < 8; i++) r += sred[i];
        sbro[1] = 1.0f / r;
    }
    __syncthreads();
    const float rinv = sbro[1];

    __half hi[4], lo[4];
#pragma unroll
    for (int j = 0; j < 4; j++) {
        float w = e[j] * rinv;
        hi[j] = __float2half_rn(w);
        lo[j] = __float2half_rn(w - __half2float(hi[j]));
    }
    __half* dh = g_wh + (size_t)m * KCB + t * 4;
    __half* dl = g_wl + (size_t)m * KCB + t * 4;
    *reinterpret_cast<__half2*>(dh)     = __half2(hi[0], hi[1]);
    *reinterpret_cast<__half2*>(dh + 2) = __half2(hi[2], hi[3]);
    *reinterpret_cast<__half2*>(dl)     = __half2(lo[0], lo[1]);
    *reinterpret_cast<__half2*>(dl + 2) = __half2(lo[2], lo[3]);
}

// ---------------------------------------------------------------------------
// GEMM2 (fused): Q[M,D] = (Wh + Wl) @ Cb^T, two fp16 MMA chains sharing the
// B fragments. BK=16, tiles [Wh|Wl|Ch] x 2 buffers = 36KB static smem.
// Single write pass (no RMW).
// ---------------------------------------------------------------------------
__global__ __launch_bounds__(256) void k_gemm2(float* __restrict__ out)
{
    __shared__ __align__(1024) char sm[2 * 3 * TILE2];   // 36864 B
    const uint32_t sbase = s2u(sm);
    const int tid  = threadIdx.x;
    const int lane = tid & 31;
    const int warp = tid >> 5;
    const int wm = (warp >> 2) * 64;
    const int wn = (warp & 3) * 32;
    const int bm = blockIdx.y * 128, bn = blockIdx.x * 128;

    FragC acc[4][2];
#pragma unroll
    for (int i = 0; i < 4; i++)
#pragma unroll
        for (int j = 0; j < 2; j++) wmma::fill_fragment(acc[i][j], 0.0f);

    load_tile16(sbase,             g_wh,   bm, 0, tid);
    load_tile16(sbase + TILE2,     g_wl,   bm, 0, tid);
    load_tile16(sbase + 2 * TILE2, g_cbth, bn, 0, tid);
    CP_COMMIT();

    for (int s = 0; s < 64; s++) {
        const uint32_t buf = sbase + (uint32_t)(s & 1) * (3 * TILE2);
        if (s + 1 < 64) {
            const uint32_t nb = sbase + (uint32_t)((s + 1) & 1) * (3 * TILE2);
            const int k1 = (s + 1) * BK2;
            load_tile16(nb,             g_wh,   bm, k1, tid);
            load_tile16(nb + TILE2,     g_wl,   bm, k1, tid);
            load_tile16(nb + 2 * TILE2, g_cbth, bn, k1, tid);
            CP_COMMIT();
            CP_WAIT1();
        } else {
            CP_WAIT0();
        }
        __syncthreads();

        const __half* Whs = (const __half*)(sm + (buf - sbase));
        const __half* Wls = (const __half*)(sm + (buf - sbase) + TILE2);
        const __half* Chs = (const __half*)(sm + (buf - sbase) + 2 * TILE2);

        FragB b[2];
#pragma unroll
        for (int j = 0; j < 2; j++)
            wmma::load_matrix_sync(b[j], Chs + (wn + j * 16) * LDT2, LDT2);
        {
            FragA a[4];
#pragma unroll
            for (int i = 0; i < 4; i++)
                wmma::load_matrix_sync(a[i], Whs + (wm + i * 16) * LDT2, LDT2);
#pragma unroll
            for (int i = 0; i < 4; i++)
#pragma unroll
                for (int j = 0; j < 2; j++)
                    wmma::mma_sync(acc[i][j], a[i], b[j], acc[i][j]);
        }
        {
            FragA a[4];
#pragma unroll
            for (int i = 0; i < 4; i++)
                wmma::load_matrix_sync(a[i], Wls + (wm + i * 16) * LDT2, LDT2);
#pragma unroll
            for (int i = 0; i < 4; i++)
#pragma unroll
                for (int j = 0; j < 2; j++)
                    wmma::mma_sync(acc[i][j], a[i], b[j], acc[i][j]);
        }
        __syncthreads();
    }

    __syncthreads();
    float* stg = reinterpret_cast<float*>(sm) + warp * 256;
#pragma unroll
    for (int i = 0; i < 4; i++)
#pragma unroll
        for (int j = 0; j < 2; j++) {
            wmma::store_matrix_sync(stg, acc[i][j], 16, wmma::mem_row_major);
            __syncwarp();
            const int r  = lane >> 1;
            const int c0 = (lane & 1) * 8;
            const int m0 = bm + wm + i * 16 + r;
            const int n0 = bn + wn + j * 16 + c0;
            float* p = out + (size_t)m0 * DDIM + n0;
            *reinterpret_cast<float4*>(p) =
                make_float4(stg[r * 16 + c0 + 0], stg[r * 16 + c0 + 1],
                            stg[r * 16 + c0 + 2], stg[r * 16 + c0 + 3]);
            *reinterpret_cast<float4*>(p + 4) =
                make_float4(stg[r * 16 + c0 + 4], stg[r * 16 + c0 + 5],
                            stg[r * 16 + c0 + 6], stg[r * 16 + c0 + 7]);
            __syncwarp();
        }
}

// ---------------------------------------------------------------------------
// Host
// ---------------------------------------------------------------------------
extern "C" void kernel_launch(void* const* d_in, const int* in_sizes, int n_in,
                              void* d_out, int out_size)
{
    const float* emb = (const float*)d_in[0];   // [M, D]
    const float* cb  = (const float*)d_in[1];   // [K, D]
    const float* un  = (const float*)d_in[2];   // [M, K]

    float* quant  = (float*)d_out;                         // [M, D]
    float* logits = (float*)d_out + (size_t)M_TOK * DDIM;  // [M, K]

    k_prep_emb<<<M_TOK, 256>>>(emb);
    k_prep_cb<<<KCB, 256>>>(cb);
    k_gemm1<<<dim3(KCB / 128, M_TOK / 128), 256>>>(logits);
    k_softmax<<<M_TOK, 256>>>(logits, un);
    k_gemm2<<<dim3(DDIM / 128, M_TOK / 128), 256>>>(quant);
}